// round 15
// baseline (speedup 1.0000x reference)
#include <cuda_runtime.h>
#include <cuda_fp16.h>
#include <math.h>
#include <stdint.h>

#define BS 4096
#define CIN 256
#define INV_SQRT_HD 0.08838834764831843f

// ---- static scratch ----
static __device__ float  g_k[268435456];    // [BS*128, 512] fp32
static __device__ float  g_v[268435456];    // [BS*128, 512] fp32
static __device__ float  g_q[67108864];     // [BS*32, 512] fp32
static __device__ __half g_eh[134217728];   // entities hi
static __device__ __half g_el[134217728];   // entities lo
static __device__ __half g_ath[67108864];   // attention out hi [BS*32, 512]
static __device__ __half g_atl[67108864];   // attention out lo
static __device__ __half g_wih[393216];     // W_in hi
static __device__ __half g_wil[393216];     // W_in lo
static __device__ __half g_woh[262144];     // W_out hi
static __device__ __half g_wol[262144];     // W_out lo

// =====================================================================
// helpers
// =====================================================================
__device__ __forceinline__ uint32_t cvta_shared_u32(const void* p) {
    uint32_t r;
    asm("{ .reg .u64 t; cvta.to.shared.u64 t, %1; cvt.u32.u64 %0, t; }" : "=r"(r) : "l"(p));
    return r;
}
__device__ __forceinline__ void mma16816(float* c, const uint32_t* a, const uint32_t* b) {
    asm volatile(
        "mma.sync.aligned.m16n8k16.row.col.f32.f16.f16.f32 "
        "{%0,%1,%2,%3}, {%4,%5,%6,%7}, {%8,%9}, {%0,%1,%2,%3};"
        : "+f"(c[0]), "+f"(c[1]), "+f"(c[2]), "+f"(c[3])
        : "r"(a[0]), "r"(a[1]), "r"(a[2]), "r"(a[3]), "r"(b[0]), "r"(b[1]));
}
__device__ __forceinline__ void ldsm_x4(uint32_t* d, uint32_t addr) {
    asm volatile("ldmatrix.sync.aligned.m8n8.x4.shared.b16 {%0,%1,%2,%3}, [%4];"
        : "=r"(d[0]), "=r"(d[1]), "=r"(d[2]), "=r"(d[3]) : "r"(addr));
}
__device__ __forceinline__ void split2(float x, __half& h, __half& l) {
    h = __float2half_rn(x);
    l = __float2half_rn(x - __half2float(h));
}
__device__ __forceinline__ uint32_t packh2(__half a, __half b) {
    __half2 t = __halves2half2(a, b);
    return *(uint32_t*)&t;
}
__device__ __forceinline__ void cp16(uint32_t dst, const void* src) {
    asm volatile("cp.async.cg.shared.global [%0], [%1], 16;" :: "r"(dst), "l"(src));
}

// =====================================================================
// split kernel: fp32 -> (hi, lo) fp16 arrays, vectorized x4
// =====================================================================
__global__ void __launch_bounds__(256) split_kernel(
    const float4* __restrict__ src, __half* __restrict__ h, __half* __restrict__ l, int n4)
{
    int i = blockIdx.x * 256 + threadIdx.x;
    if (i >= n4) return;
    float4 v = src[i];
    __half h0, h1, h2, h3, l0, l1, l2, l3;
    split2(v.x, h0, l0); split2(v.y, h1, l1);
    split2(v.z, h2, l2); split2(v.w, h3, l3);
    ((uint2*)h)[i] = make_uint2(packh2(h0, h1), packh2(h2, h3));
    ((uint2*)l)[i] = make_uint2(packh2(l0, l1), packh2(l2, l3));
}

// =====================================================================
// 3xFP16 HMMA GEMM, pre-split operands, cp.async 2-stage double buffer,
// ldmatrix fragment loads, 2 CTAs/SM.
// C[M,N] = A[M,K] @ B[N,K]^T. Tile 128x128, BK=32, 256 threads.
// MODE 0: KV proj (gn<512 -> C else C2 col-512)
// MODE 1: Q proj (A row remap m -> (m/32)*128 + m%32)
// MODE 2: out proj (+bias, postmask zero)
// SMEM per stage (halves, row stride 40): AH[128][40] AL BH BL
//   = 4 * 5120 halves = 40960 B; 2 stages = 81920 B.
// =====================================================================
#define ASTR 40
#define STG_H 20480           // halves per stage
#define STG_B 40960           // bytes per stage
#define GEMM_SMEM 81920
#define DSTR 136

template<int MODE, int KDIM>
__global__ void __launch_bounds__(256, 2) gemm_hmma(
    const __half* __restrict__ Ah, const __half* __restrict__ Al,
    const __half* __restrict__ Bh, const __half* __restrict__ Bl,
    float* __restrict__ C, float* __restrict__ C2,
    const float* __restrict__ bias, const int* __restrict__ postmask)
{
    extern __shared__ __half sh[];
    const uint32_t sbase = cvta_shared_u32(sh);
    const int tid  = threadIdx.x;
    const int m0   = blockIdx.y * 128;
    const int n0   = blockIdx.x * 128;
    const int wid  = tid >> 5, lane = tid & 31;
    const int wm   = wid & 1;
    const int wn   = wid >> 1;
    const int r    = lane >> 2;
    const int tig  = lane & 3;

    constexpr int NCH = KDIM / 32;

    // ldmatrix per-lane offsets
    const int a_row = (lane & 7) + ((lane >> 3) & 1) * 8;   // quads 0/2: +0, 1/3: +8
    const int a_ko  = (lane >> 4) * 8;                      // quads 2,3: k+8
    const int b_row = (lane & 7) + ((lane >> 4) & 1) * 8;   // quads 2,3: next n-tile
    const int b_ko  = ((lane >> 3) & 1) * 8;                // quads 1,3: k+8

    auto stage_copy = [&](int ch, int s) {
        const int k0 = ch * 32;
#pragma unroll
        for (int i = 0; i < 8; ++i) {
            int idx = tid + 256 * i;
            int mat = idx >> 9;
            int row = (idx >> 2) & 127;
            int c16 = idx & 3;
            const __half* src;
            if (mat <= 1) {
                int gm = m0 + row;
                long arow = (MODE == 1) ? ((long)(gm >> 5) * 128 + (gm & 31)) : (long)gm;
                src = (mat == 0 ? Ah : Al) + arow * KDIM + k0 + c16 * 8;
            } else {
                src = (mat == 2 ? Bh : Bl) + (long)(n0 + row) * KDIM + k0 + c16 * 8;
            }
            cp16(sbase + s * STG_B + mat * 10240 + row * 80 + c16 * 16, src);
        }
        asm volatile("cp.async.commit_group;" ::: "memory");
    };

    float acc[4][4][4];
#pragma unroll
    for (int mt = 0; mt < 4; ++mt)
#pragma unroll
        for (int nt = 0; nt < 4; ++nt)
#pragma unroll
            for (int j = 0; j < 4; ++j) acc[mt][nt][j] = 0.0f;

    stage_copy(0, 0);

    for (int ch = 0; ch < NCH; ++ch) {
        if (ch + 1 < NCH) {
            stage_copy(ch + 1, (ch + 1) & 1);
            asm volatile("cp.async.wait_group 1;" ::: "memory");
        } else {
            asm volatile("cp.async.wait_group 0;" ::: "memory");
        }
        __syncthreads();

        const int sb = (ch & 1) * STG_H;  // stage base in halves
#pragma unroll
        for (int ks = 0; ks < 2; ++ks) {
            const int kc = ks * 16;
            uint32_t ah[4][4], al[4][4], bh[2][4], bl[2][4];
#pragma unroll
            for (int p = 0; p < 2; ++p) {
                uint32_t boff = (uint32_t)(sb + (wn * 32 + p * 16 + b_row) * ASTR + kc + b_ko);
                ldsm_x4(bh[p], sbase + 2u * (boff + 10240u));
                ldsm_x4(bl[p], sbase + 2u * (boff + 15360u));
            }
#pragma unroll
            for (int mt = 0; mt < 4; ++mt) {
                uint32_t aoff = (uint32_t)(sb + (wm * 64 + mt * 16 + a_row) * ASTR + kc + a_ko);
                ldsm_x4(ah[mt], sbase + 2u * aoff);
                ldsm_x4(al[mt], sbase + 2u * (aoff + 5120u));
            }
            // three passes of 16 independent MMAs (no acc dependency chains)
#pragma unroll
            for (int mt = 0; mt < 4; ++mt)
#pragma unroll
                for (int nt = 0; nt < 4; ++nt) mma16816(acc[mt][nt], ah[mt], &bh[nt >> 1][(nt & 1) * 2]);
#pragma unroll
            for (int mt = 0; mt < 4; ++mt)
#pragma unroll
                for (int nt = 0; nt < 4; ++nt) mma16816(acc[mt][nt], ah[mt], &bl[nt >> 1][(nt & 1) * 2]);
#pragma unroll
            for (int mt = 0; mt < 4; ++mt)
#pragma unroll
                for (int nt = 0; nt < 4; ++nt) mma16816(acc[mt][nt], al[mt], &bh[nt >> 1][(nt & 1) * 2]);
        }
        __syncthreads();   // protect stage buffer before next iter's cp.async overwrite
    }

    // ---- epilogue: regs -> smem (row-major fp32) -> coalesced gmem ----
    float* sD = (float*)sh;
#pragma unroll
    for (int mt = 0; mt < 4; ++mt) {
#pragma unroll
        for (int nt = 0; nt < 4; ++nt) {
            int row = wm * 64 + mt * 16 + r;
            int col = wn * 32 + nt * 8 + tig * 2;
            *(float2*)&sD[row * DSTR + col]       = make_float2(acc[mt][nt][0], acc[mt][nt][1]);
            *(float2*)&sD[(row + 8) * DSTR + col] = make_float2(acc[mt][nt][2], acc[mt][nt][3]);
        }
    }
    __syncthreads();

#pragma unroll 4
    for (int i = 0; i < 16; ++i) {
        int idx = tid + 256 * i;
        int row = idx >> 5;
        int cc  = idx & 31;
        float4 v = *(float4*)&sD[row * DSTR + cc * 4];
        int gm = m0 + row, gn = n0 + cc * 4;
        if (MODE == 2) {
            if (postmask[gm]) { v.x = v.y = v.z = v.w = 0.0f; }
            else {
                float4 bb = *(const float4*)(bias + gn);
                v.x += bb.x; v.y += bb.y; v.z += bb.z; v.w += bb.w;
            }
            *(float4*)(C + (long)gm * 512 + gn) = v;
        } else if (MODE == 0) {
            if (gn < 512) *(float4*)(C  + (long)gm * 512 + gn)       = v;
            else          *(float4*)(C2 + (long)gm * 512 + gn - 512) = v;
        } else {
            *(float4*)(C + (long)gm * 512 + gn) = v;
        }
    }
}

// =====================================================================
// Attention: one CTA per (b, h). V is NOT staged in smem (PV loop reads
// gmem directly -> L1 broadcast across warps); smem 107.5 KB -> 2 CTA/SM.
// Output written as split fp16 (hi/lo) for the out-projection GEMM.
// =====================================================================
#define SROW 140
#define SM_Q 0
#define SM_K (32 * SROW)
#define SM_P (160 * SROW)
#define ATT_SMEM (192 * SROW * 4)

__global__ void __launch_bounds__(256, 2) attn_kernel(
    const float* __restrict__ gq, const float* __restrict__ gk,
    const float* __restrict__ gv, const int* __restrict__ premask,
    __half* __restrict__ ath, __half* __restrict__ atl)
{
    extern __shared__ float sm[];
    const int b = blockIdx.x, h = blockIdx.y;
    const int tid = threadIdx.x;
    const int lane = tid & 31;
    const int q0 = (tid >> 5) * 4;

    for (int i = tid; i < 32 * 32; i += 256) {
        int q = i >> 5, d4 = i & 31;
        *(float4*)&sm[SM_Q + q * SROW + d4 * 4] =
            *(const float4*)(gq + ((long)(b * 32 + q)) * 512 + h * 128 + d4 * 4);
    }
    for (int i = tid; i < 128 * 32; i += 256) {
        int e = i >> 5, d4 = i & 31;
        long off = ((long)(b * 128 + e)) * 512 + h * 128 + d4 * 4;
        *(float4*)&sm[SM_K + e * SROW + d4 * 4] = *(const float4*)(gk + off);
    }
    __syncthreads();

    float lg[4][4];
    {
        float acc[4][4];
#pragma unroll
        for (int qi = 0; qi < 4; ++qi)
#pragma unroll
            for (int j = 0; j < 4; ++j) acc[qi][j] = 0.0f;
        for (int d4 = 0; d4 < 32; ++d4) {
            float4 qa[4], ka[4];
#pragma unroll
            for (int qi = 0; qi < 4; ++qi) qa[qi] = *(const float4*)&sm[SM_Q + (q0 + qi) * SROW + d4 * 4];
#pragma unroll
            for (int j = 0; j < 4; ++j) ka[j] = *(const float4*)&sm[SM_K + (lane + 32 * j) * SROW + d4 * 4];
#pragma unroll
            for (int qi = 0; qi < 4; ++qi)
#pragma unroll
                for (int j = 0; j < 4; ++j)
                    acc[qi][j] += qa[qi].x * ka[j].x + qa[qi].y * ka[j].y
                                + qa[qi].z * ka[j].z + qa[qi].w * ka[j].w;
        }
        const int* pm = premask + (long)b * (32 * 128);
#pragma unroll
        for (int qi = 0; qi < 4; ++qi)
#pragma unroll
            for (int j = 0; j < 4; ++j) {
                int e = lane + 32 * j;
                lg[qi][j] = pm[(q0 + qi) * 128 + e] ? -INFINITY : acc[qi][j] * INV_SQRT_HD;
            }
    }

#pragma unroll
    for (int qi = 0; qi < 4; ++qi) {
        float mx = fmaxf(fmaxf(lg[qi][0], lg[qi][1]), fmaxf(lg[qi][2], lg[qi][3]));
#pragma unroll
        for (int off = 16; off > 0; off >>= 1)
            mx = fmaxf(mx, __shfl_xor_sync(0xFFFFFFFFu, mx, off));
        float p[4], s = 0.0f;
        if (mx == -INFINITY) {
            p[0] = p[1] = p[2] = p[3] = 0.0f;
        } else {
#pragma unroll
            for (int j = 0; j < 4; ++j) { p[j] = __expf(lg[qi][j] - mx); s += p[j]; }
        }
#pragma unroll
        for (int off = 16; off > 0; off >>= 1)
            s += __shfl_xor_sync(0xFFFFFFFFu, s, off);
        float inv = (mx == -INFINITY) ? 0.0f : (1.0f / s);
#pragma unroll
        for (int j = 0; j < 4; ++j)
            sm[SM_P + (q0 + qi) * SROW + lane + 32 * j] = p[j] * inv;
    }
    __syncthreads();

    float acc2[4][4];
#pragma unroll
    for (int qi = 0; qi < 4; ++qi)
#pragma unroll
        for (int j = 0; j < 4; ++j) acc2[qi][j] = 0.0f;
    const float* vbase = gv + ((long)b * 128) * 512 + h * 128 + lane;
#pragma unroll 4
    for (int e = 0; e < 128; ++e) {
        float pf[4], vv[4];
#pragma unroll
        for (int qi = 0; qi < 4; ++qi) pf[qi] = sm[SM_P + (q0 + qi) * SROW + e];
#pragma unroll
        for (int j = 0; j < 4; ++j) vv[j] = vbase[(long)e * 512 + 32 * j];
#pragma unroll
        for (int qi = 0; qi < 4; ++qi)
#pragma unroll
            for (int j = 0; j < 4; ++j) acc2[qi][j] += pf[qi] * vv[j];
    }
#pragma unroll
    for (int qi = 0; qi < 4; ++qi)
#pragma unroll
        for (int j = 0; j < 4; ++j) {
            long idx = ((long)(b * 32 + q0 + qi)) * 512 + h * 128 + lane + 32 * j;
            __half hh, ll;
            split2(acc2[qi][j], hh, ll);
            ath[idx] = hh; atl[idx] = ll;
        }
}

extern "C" void kernel_launch(void* const* d_in, const int* in_sizes, int n_in,
                              void* d_out, int out_size) {
    const float* entities = nullptr; const int* pre_mask = nullptr;
    const int* post_mask = nullptr;  const float* W_in = nullptr;
    const float* W_out = nullptr;    const float* b_out = nullptr;
    for (int i = 0; i < n_in; ++i) {
        switch (in_sizes[i]) {
            case 134217728: entities  = (const float*)d_in[i]; break;
            case 16777216:  pre_mask  = (const int*)d_in[i];   break;
            case 131072:    post_mask = (const int*)d_in[i];   break;
            case 393216:    W_in      = (const float*)d_in[i]; break;
            case 262144:    W_out     = (const float*)d_in[i]; break;
            case 512:       b_out     = (const float*)d_in[i]; break;
        }
    }
    float* out = (float*)d_out;

    float *pk, *pv, *pq;
    __half *peh, *pel, *path, *patl, *pwih, *pwil, *pwoh, *pwol;
    cudaGetSymbolAddress((void**)&pk,   g_k);
    cudaGetSymbolAddress((void**)&pv,   g_v);
    cudaGetSymbolAddress((void**)&pq,   g_q);
    cudaGetSymbolAddress((void**)&peh,  g_eh);
    cudaGetSymbolAddress((void**)&pel,  g_el);
    cudaGetSymbolAddress((void**)&path, g_ath);
    cudaGetSymbolAddress((void**)&patl, g_atl);
    cudaGetSymbolAddress((void**)&pwih, g_wih);
    cudaGetSymbolAddress((void**)&pwil, g_wil);
    cudaGetSymbolAddress((void**)&pwoh, g_woh);
    cudaGetSymbolAddress((void**)&pwol, g_wol);

    cudaFuncSetAttribute(gemm_hmma<0, 256>, cudaFuncAttributeMaxDynamicSharedMemorySize, GEMM_SMEM);
    cudaFuncSetAttribute(gemm_hmma<1, 256>, cudaFuncAttributeMaxDynamicSharedMemorySize, GEMM_SMEM);
    cudaFuncSetAttribute(gemm_hmma<2, 512>, cudaFuncAttributeMaxDynamicSharedMemorySize, GEMM_SMEM);
    cudaFuncSetAttribute(attn_kernel, cudaFuncAttributeMaxDynamicSharedMemorySize, ATT_SMEM);

    // pre-split all fp32 operands into fp16 hi/lo (memory-bound, ~0.2 ms)
    split_kernel<<<131072, 256>>>((const float4*)entities, peh, pel, 33554432);
    split_kernel<<<384, 256>>>((const float4*)W_in, pwih, pwil, 98304);
    split_kernel<<<256, 256>>>((const float4*)W_out, pwoh, pwol, 65536);

    // K/V projection: 524288 rows x [256 -> 1024] (W_in rows 512..1535)
    gemm_hmma<0, 256><<<dim3(8, 4096), 256, GEMM_SMEM>>>(
        peh, pel, pwih + 512 * CIN, pwil + 512 * CIN, pk, pv, nullptr, nullptr);
    // Q projection: 131072 rows (remapped) x [256 -> 512]
    gemm_hmma<1, 256><<<dim3(4, 1024), 256, GEMM_SMEM>>>(
        peh, pel, pwih, pwil, pq, nullptr, nullptr, nullptr);
    // attention (emits split fp16)
    attn_kernel<<<dim3(BS, 4), 256, ATT_SMEM>>>(pq, pk, pv, pre_mask, path, patl);
    // output projection + bias + post mask
    gemm_hmma<2, 512><<<dim3(4, 1024), 256, GEMM_SMEM>>>(
        path, patl, pwoh, pwol, out, nullptr, b_out, post_mask);
}

// round 17
// speedup vs baseline: 1.8369x; 1.8369x over previous
#include <cuda_runtime.h>
#include <cuda_fp16.h>
#include <math.h>
#include <stdint.h>

#define BS 4096
#define CIN 256
#define INV_SQRT_HD 0.08838834764831843f

// ---- static scratch ----
static __device__ float  g_k[268435456];    // [BS*128, 512] fp32
static __device__ float  g_v[268435456];    // [BS*128, 512] fp32
static __device__ float  g_q[67108864];     // [BS*32, 512] fp32
static __device__ __half g_eh[134217728];   // entities hi
static __device__ __half g_el[134217728];   // entities lo
static __device__ __half g_ath[67108864];   // attention out hi [BS*32, 512]
static __device__ __half g_atl[67108864];   // attention out lo
static __device__ __half g_wih[393216];     // W_in hi
static __device__ __half g_wil[393216];     // W_in lo
static __device__ __half g_woh[262144];     // W_out hi
static __device__ __half g_wol[262144];     // W_out lo

// =====================================================================
// helpers
// =====================================================================
__device__ __forceinline__ uint32_t cvta_shared_u32(const void* p) {
    uint32_t r;
    asm("{ .reg .u64 t; cvta.to.shared.u64 t, %1; cvt.u32.u64 %0, t; }" : "=r"(r) : "l"(p));
    return r;
}
__device__ __forceinline__ void mma16816(float* c, const uint32_t* a, const uint32_t* b) {
    asm volatile(
        "mma.sync.aligned.m16n8k16.row.col.f32.f16.f16.f32 "
        "{%0,%1,%2,%3}, {%4,%5,%6,%7}, {%8,%9}, {%0,%1,%2,%3};"
        : "+f"(c[0]), "+f"(c[1]), "+f"(c[2]), "+f"(c[3])
        : "r"(a[0]), "r"(a[1]), "r"(a[2]), "r"(a[3]), "r"(b[0]), "r"(b[1]));
}
__device__ __forceinline__ void split2(float x, __half& h, __half& l) {
    h = __float2half_rn(x);
    l = __float2half_rn(x - __half2float(h));
}
__device__ __forceinline__ uint32_t packh2(__half a, __half b) {
    __half2 t = __halves2half2(a, b);
    return *(uint32_t*)&t;
}
__device__ __forceinline__ void cp16(uint32_t dst, const void* src) {
    asm volatile("cp.async.cg.shared.global [%0], [%1], 16;" :: "r"(dst), "l"(src));
}

// =====================================================================
// split kernel: fp32 -> (hi, lo) fp16 arrays, vectorized x4
// =====================================================================
__global__ void __launch_bounds__(256) split_kernel(
    const float4* __restrict__ src, __half* __restrict__ h, __half* __restrict__ l, int n4)
{
    int i = blockIdx.x * 256 + threadIdx.x;
    if (i >= n4) return;
    float4 v = src[i];
    __half h0, h1, h2, h3, l0, l1, l2, l3;
    split2(v.x, h0, l0); split2(v.y, h1, l1);
    split2(v.z, h2, l2); split2(v.w, h3, l3);
    ((uint2*)h)[i] = make_uint2(packh2(h0, h1), packh2(h2, h3));
    ((uint2*)l)[i] = make_uint2(packh2(l0, l1), packh2(l2, l3));
}

// =====================================================================
// 3xFP16 HMMA GEMM (R14 version, verbatim): pre-split operands,
// cp.async 2-stage double buffer, scalar LDS fragment loads, 2 CTAs/SM.
// C[M,N] = A[M,K] @ B[N,K]^T. Tile 128x128, BK=32, 256 threads.
// MODE 0: KV proj (gn<512 -> C else C2 col-512)
// MODE 1: Q proj (A row remap m -> (m/32)*128 + m%32)
// MODE 2: out proj (+bias, postmask zero)
// =====================================================================
#define ASTR 40
#define STG_H 20480           // halves per stage
#define STG_B 40960           // bytes per stage
#define GEMM_SMEM 81920
#define DSTR 136

template<int MODE, int KDIM>
__global__ void __launch_bounds__(256, 2) gemm_hmma(
    const __half* __restrict__ Ah, const __half* __restrict__ Al,
    const __half* __restrict__ Bh, const __half* __restrict__ Bl,
    float* __restrict__ C, float* __restrict__ C2,
    const float* __restrict__ bias, const int* __restrict__ postmask)
{
    extern __shared__ __half sh[];
    const uint32_t sbase = cvta_shared_u32(sh);
    const int tid  = threadIdx.x;
    const int m0   = blockIdx.y * 128;
    const int n0   = blockIdx.x * 128;
    const int wid  = tid >> 5, lane = tid & 31;
    const int wm   = wid & 1;
    const int wn   = wid >> 1;
    const int r    = lane >> 2;
    const int tig  = lane & 3;

    constexpr int NCH = KDIM / 32;

    auto stage_copy = [&](int ch, int s) {
        const int k0 = ch * 32;
#pragma unroll
        for (int i = 0; i < 8; ++i) {
            int idx = tid + 256 * i;
            int mat = idx >> 9;
            int row = (idx >> 2) & 127;
            int c16 = idx & 3;
            const __half* src;
            if (mat <= 1) {
                int gm = m0 + row;
                long arow = (MODE == 1) ? ((long)(gm >> 5) * 128 + (gm & 31)) : (long)gm;
                src = (mat == 0 ? Ah : Al) + arow * KDIM + k0 + c16 * 8;
            } else {
                src = (mat == 2 ? Bh : Bl) + (long)(n0 + row) * KDIM + k0 + c16 * 8;
            }
            cp16(sbase + s * STG_B + mat * 10240 + row * 80 + c16 * 16, src);
        }
        asm volatile("cp.async.commit_group;" ::: "memory");
    };

    float acc[4][4][4];
#pragma unroll
    for (int mt = 0; mt < 4; ++mt)
#pragma unroll
        for (int nt = 0; nt < 4; ++nt)
#pragma unroll
            for (int j = 0; j < 4; ++j) acc[mt][nt][j] = 0.0f;

    stage_copy(0, 0);

    for (int ch = 0; ch < NCH; ++ch) {
        if (ch + 1 < NCH) {
            stage_copy(ch + 1, (ch + 1) & 1);
            asm volatile("cp.async.wait_group 1;" ::: "memory");
        } else {
            asm volatile("cp.async.wait_group 0;" ::: "memory");
        }
        __syncthreads();

        const int sb = (ch & 1) * STG_H;  // stage base in halves
#pragma unroll
        for (int ks = 0; ks < 2; ++ks) {
            const int kc = ks * 16 + tig * 2;
            uint32_t ah[4][4], al[4][4], bh[4][2], bl[4][2];
#pragma unroll
            for (int nt = 0; nt < 4; ++nt) {
                int n = wn * 32 + nt * 8 + r;
                bh[nt][0] = *(const uint32_t*)&sh[sb + 10240 + n * ASTR + kc];
                bh[nt][1] = *(const uint32_t*)&sh[sb + 10240 + n * ASTR + kc + 8];
                bl[nt][0] = *(const uint32_t*)&sh[sb + 15360 + n * ASTR + kc];
                bl[nt][1] = *(const uint32_t*)&sh[sb + 15360 + n * ASTR + kc + 8];
            }
#pragma unroll
            for (int mt = 0; mt < 4; ++mt) {
                int ra = wm * 64 + mt * 16 + r;
                ah[mt][0] = *(const uint32_t*)&sh[sb + ra * ASTR + kc];
                ah[mt][1] = *(const uint32_t*)&sh[sb + (ra + 8) * ASTR + kc];
                ah[mt][2] = *(const uint32_t*)&sh[sb + ra * ASTR + kc + 8];
                ah[mt][3] = *(const uint32_t*)&sh[sb + (ra + 8) * ASTR + kc + 8];
                al[mt][0] = *(const uint32_t*)&sh[sb + 5120 + ra * ASTR + kc];
                al[mt][1] = *(const uint32_t*)&sh[sb + 5120 + (ra + 8) * ASTR + kc];
                al[mt][2] = *(const uint32_t*)&sh[sb + 5120 + ra * ASTR + kc + 8];
                al[mt][3] = *(const uint32_t*)&sh[sb + 5120 + (ra + 8) * ASTR + kc + 8];
            }
#pragma unroll
            for (int mt = 0; mt < 4; ++mt)
#pragma unroll
                for (int nt = 0; nt < 4; ++nt) mma16816(acc[mt][nt], ah[mt], bh[nt]);
#pragma unroll
            for (int mt = 0; mt < 4; ++mt)
#pragma unroll
                for (int nt = 0; nt < 4; ++nt) mma16816(acc[mt][nt], ah[mt], bl[nt]);
#pragma unroll
            for (int mt = 0; mt < 4; ++mt)
#pragma unroll
                for (int nt = 0; nt < 4; ++nt) mma16816(acc[mt][nt], al[mt], bh[nt]);
        }
        __syncthreads();
    }

    // ---- epilogue: regs -> smem (row-major fp32) -> coalesced gmem ----
    float* sD = (float*)sh;
#pragma unroll
    for (int mt = 0; mt < 4; ++mt) {
#pragma unroll
        for (int nt = 0; nt < 4; ++nt) {
            int row = wm * 64 + mt * 16 + r;
            int col = wn * 32 + nt * 8 + tig * 2;
            *(float2*)&sD[row * DSTR + col]       = make_float2(acc[mt][nt][0], acc[mt][nt][1]);
            *(float2*)&sD[(row + 8) * DSTR + col] = make_float2(acc[mt][nt][2], acc[mt][nt][3]);
        }
    }
    __syncthreads();

#pragma unroll 4
    for (int i = 0; i < 16; ++i) {
        int idx = tid + 256 * i;
        int row = idx >> 5;
        int cc  = idx & 31;
        float4 v = *(float4*)&sD[row * DSTR + cc * 4];
        int gm = m0 + row, gn = n0 + cc * 4;
        if (MODE == 2) {
            if (postmask[gm]) { v.x = v.y = v.z = v.w = 0.0f; }
            else {
                float4 bb = *(const float4*)(bias + gn);
                v.x += bb.x; v.y += bb.y; v.z += bb.z; v.w += bb.w;
            }
            *(float4*)(C + (long)gm * 512 + gn) = v;
        } else if (MODE == 0) {
            if (gn < 512) *(float4*)(C  + (long)gm * 512 + gn)       = v;
            else          *(float4*)(C2 + (long)gm * 512 + gn - 512) = v;
        } else {
            *(float4*)(C + (long)gm * 512 + gn) = v;
        }
    }
}

// =====================================================================
// Attention: one CTA per (b, h), 256 threads, 2 CTAs/SM.
// K and V SHARE one 128-row smem buffer: V is cp.async-staged into it
// after logits finish reading K, overlapping with softmax.
// smem: Q[32] + KV[128] + P[32] rows of SROW floats = 107520 B.
// Each row = 128 floats = 512 B = 32 x 16B chunks.
// =====================================================================
#define SROW 140
#define SM_Q 0
#define SM_KV (32 * SROW)
#define SM_P (160 * SROW)
#define ATT_SMEM (192 * SROW * 4)

__global__ void __launch_bounds__(256, 2) attn_kernel(
    const float* __restrict__ gq, const float* __restrict__ gk,
    const float* __restrict__ gv, const int* __restrict__ premask,
    __half* __restrict__ ath, __half* __restrict__ atl)
{
    extern __shared__ float sm[];
    const uint32_t sbase = cvta_shared_u32(sm);
    const int b = blockIdx.x, h = blockIdx.y;
    const int tid = threadIdx.x;
    const int lane = tid & 31;
    const int q0 = (tid >> 5) * 4;

    // ---- stage Q (32 rows x 32 chunks = 1024) + K (128 x 32 = 4096) ----
#pragma unroll
    for (int i = 0; i < 4; ++i) {
        int idx = tid + 256 * i;
        int row = idx >> 5, c16 = idx & 31;
        cp16(sbase + 4u * (SM_Q + row * SROW + c16 * 4),
             gq + ((long)(b * 32 + row)) * 512 + h * 128 + c16 * 4);
    }
#pragma unroll
    for (int i = 0; i < 16; ++i) {
        int idx = tid + 256 * i;
        int row = idx >> 5, c16 = idx & 31;
        cp16(sbase + 4u * (SM_KV + row * SROW + c16 * 4),
             gk + ((long)(b * 128 + row)) * 512 + h * 128 + c16 * 4);
    }
    asm volatile("cp.async.commit_group;" ::: "memory");
    asm volatile("cp.async.wait_group 0;" ::: "memory");
    __syncthreads();

    // ---- logits: acc[qi][j] = Q[q0+qi] . K[lane+32j] ----
    float lg[4][4];
    {
        float acc[4][4];
#pragma unroll
        for (int qi = 0; qi < 4; ++qi)
#pragma unroll
            for (int j = 0; j < 4; ++j) acc[qi][j] = 0.0f;
        for (int d4 = 0; d4 < 32; ++d4) {
            float4 qa[4], ka[4];
#pragma unroll
            for (int qi = 0; qi < 4; ++qi) qa[qi] = *(const float4*)&sm[SM_Q + (q0 + qi) * SROW + d4 * 4];
#pragma unroll
            for (int j = 0; j < 4; ++j) ka[j] = *(const float4*)&sm[SM_KV + (lane + 32 * j) * SROW + d4 * 4];
#pragma unroll
            for (int qi = 0; qi < 4; ++qi)
#pragma unroll
                for (int j = 0; j < 4; ++j)
                    acc[qi][j] += qa[qi].x * ka[j].x + qa[qi].y * ka[j].y
                                + qa[qi].z * ka[j].z + qa[qi].w * ka[j].w;
        }
        const int* pm = premask + (long)b * (32 * 128);
#pragma unroll
        for (int qi = 0; qi < 4; ++qi)
#pragma unroll
            for (int j = 0; j < 4; ++j) {
                int e = lane + 32 * j;
                lg[qi][j] = pm[(q0 + qi) * 128 + e] ? -INFINITY : acc[qi][j] * INV_SQRT_HD;
            }
    }
    __syncthreads();   // all warps done reading K -> KV buffer reusable

    // ---- stage V into the KV buffer (overlaps with softmax below) ----
#pragma unroll
    for (int i = 0; i < 16; ++i) {
        int idx = tid + 256 * i;
        int row = idx >> 5, c16 = idx & 31;
        cp16(sbase + 4u * (SM_KV + row * SROW + c16 * 4),
             gv + ((long)(b * 128 + row)) * 512 + h * 128 + c16 * 4);
    }
    asm volatile("cp.async.commit_group;" ::: "memory");

    // ---- softmax (registers + shuffles), write P (warp-private rows) ----
#pragma unroll
    for (int qi = 0; qi < 4; ++qi) {
        float mx = fmaxf(fmaxf(lg[qi][0], lg[qi][1]), fmaxf(lg[qi][2], lg[qi][3]));
#pragma unroll
        for (int off = 16; off > 0; off >>= 1)
            mx = fmaxf(mx, __shfl_xor_sync(0xFFFFFFFFu, mx, off));
        float p[4], s = 0.0f;
        if (mx == -INFINITY) {
            p[0] = p[1] = p[2] = p[3] = 0.0f;
        } else {
#pragma unroll
            for (int j = 0; j < 4; ++j) { p[j] = __expf(lg[qi][j] - mx); s += p[j]; }
        }
#pragma unroll
        for (int off = 16; off > 0; off >>= 1)
            s += __shfl_xor_sync(0xFFFFFFFFu, s, off);
        float inv = (mx == -INFINITY) ? 0.0f : (1.0f / s);
#pragma unroll
        for (int j = 0; j < 4; ++j)
            sm[SM_P + (q0 + qi) * SROW + lane + 32 * j] = p[j] * inv;
    }
    asm volatile("cp.async.wait_group 0;" ::: "memory");
    __syncthreads();   // V staged + all P visible

    // ---- out[q][d] = sum_e P[q][e] * V[e][d] ----
    float acc2[4][4];
#pragma unroll
    for (int qi = 0; qi < 4; ++qi)
#pragma unroll
        for (int j = 0; j < 4; ++j) acc2[qi][j] = 0.0f;
#pragma unroll 4
    for (int e = 0; e < 128; ++e) {
        float pf[4], vv[4];
#pragma unroll
        for (int qi = 0; qi < 4; ++qi) pf[qi] = sm[SM_P + (q0 + qi) * SROW + e];
#pragma unroll
        for (int j = 0; j < 4; ++j) vv[j] = sm[SM_KV + e * SROW + lane + 32 * j];
#pragma unroll
        for (int qi = 0; qi < 4; ++qi)
#pragma unroll
            for (int j = 0; j < 4; ++j) acc2[qi][j] += pf[qi] * vv[j];
    }
#pragma unroll
    for (int qi = 0; qi < 4; ++qi)
#pragma unroll
        for (int j = 0; j < 4; ++j) {
            long idx = ((long)(b * 32 + q0 + qi)) * 512 + h * 128 + lane + 32 * j;
            __half hh, ll;
            split2(acc2[qi][j], hh, ll);
            ath[idx] = hh; atl[idx] = ll;
        }
}

extern "C" void kernel_launch(void* const* d_in, const int* in_sizes, int n_in,
                              void* d_out, int out_size) {
    const float* entities = nullptr; const int* pre_mask = nullptr;
    const int* post_mask = nullptr;  const float* W_in = nullptr;
    const float* W_out = nullptr;    const float* b_out = nullptr;
    for (int i = 0; i < n_in; ++i) {
        switch (in_sizes[i]) {
            case 134217728: entities  = (const float*)d_in[i]; break;
            case 16777216:  pre_mask  = (const int*)d_in[i];   break;
            case 131072:    post_mask = (const int*)d_in[i];   break;
            case 393216:    W_in      = (const float*)d_in[i]; break;
            case 262144:    W_out     = (const float*)d_in[i]; break;
            case 512:       b_out     = (const float*)d_in[i]; break;
        }
    }
    float* out = (float*)d_out;

    float *pk, *pv, *pq;
    __half *peh, *pel, *path, *patl, *pwih, *pwil, *pwoh, *pwol;
    cudaGetSymbolAddress((void**)&pk,   g_k);
    cudaGetSymbolAddress((void**)&pv,   g_v);
    cudaGetSymbolAddress((void**)&pq,   g_q);
    cudaGetSymbolAddress((void**)&peh,  g_eh);
    cudaGetSymbolAddress((void**)&pel,  g_el);
    cudaGetSymbolAddress((void**)&path, g_ath);
    cudaGetSymbolAddress((void**)&patl, g_atl);
    cudaGetSymbolAddress((void**)&pwih, g_wih);
    cudaGetSymbolAddress((void**)&pwil, g_wil);
    cudaGetSymbolAddress((void**)&pwoh, g_woh);
    cudaGetSymbolAddress((void**)&pwol, g_wol);

    cudaFuncSetAttribute(gemm_hmma<0, 256>, cudaFuncAttributeMaxDynamicSharedMemorySize, GEMM_SMEM);
    cudaFuncSetAttribute(gemm_hmma<1, 256>, cudaFuncAttributeMaxDynamicSharedMemorySize, GEMM_SMEM);
    cudaFuncSetAttribute(gemm_hmma<2, 512>, cudaFuncAttributeMaxDynamicSharedMemorySize, GEMM_SMEM);
    cudaFuncSetAttribute(attn_kernel, cudaFuncAttributeMaxDynamicSharedMemorySize, ATT_SMEM);

    // pre-split all fp32 operands into fp16 hi/lo (memory-bound, ~0.2 ms)
    split_kernel<<<131072, 256>>>((const float4*)entities, peh, pel, 33554432);
    split_kernel<<<384, 256>>>((const float4*)W_in, pwih, pwil, 98304);
    split_kernel<<<256, 256>>>((const float4*)W_out, pwoh, pwol, 65536);

    // K/V projection: 524288 rows x [256 -> 1024] (W_in rows 512..1535)
    gemm_hmma<0, 256><<<dim3(8, 4096), 256, GEMM_SMEM>>>(
        peh, pel, pwih + 512 * CIN, pwil + 512 * CIN, pk, pv, nullptr, nullptr);
    // Q projection: 131072 rows (remapped) x [256 -> 512]
    gemm_hmma<1, 256><<<dim3(4, 1024), 256, GEMM_SMEM>>>(
        peh, pel, pwih, pwil, pq, nullptr, nullptr, nullptr);
    // attention (emits split fp16)
    attn_kernel<<<dim3(BS, 4), 256, ATT_SMEM>>>(pq, pk, pv, pre_mask, path, patl);
    // output projection + bias + post mask
    gemm_hmma<2, 512><<<dim3(4, 1024), 256, GEMM_SMEM>>>(
        path, patl, pwoh, pwol, out, nullptr, b_out, post_mask);
}